// round 15
// baseline (speedup 1.0000x reference)
#include <cuda_runtime.h>
#include <cuda_bf16.h>
#include <cuda_fp16.h>
#include <math.h>
#include <stdint.h>

#define N_NODES 40000
#define N_EDGES 640000
#define F 128
#define NCLS 16

#define EDGE_BLOCKS 2500          // ceil(640000/256)
#define CONV_BLOCKS 5000          // N_NODES*32 float4-quads / 256
#define WSP_BLOCKS 128            // 2*128*128 packed pairs / 256

// ---------------- scratch (no allocations allowed) ----------------
// g_cnt/g_cursor are zero at module load; agg16_kernel (last kernel of every
// call) re-zeroes them, so every invocation sees zeros.
__device__ float g_s[N_NODES * F];       // aggregation result / layer-2 pn
__device__ float g_h1[N_NODES * F];      // layer-0 output / layer-2 pself
__device__ float g_h2[N_NODES * F];      // layer-1 output
__device__ uint32_t g_f16[N_NODES * 64]; // fp16 copy of current agg input (half2)
__device__ int   g_cnt[N_NODES];
__device__ int   g_cur[N_NODES];
__device__ int   g_off[N_NODES];
__device__ int   g_cursor;
__device__ int2  g_edge[N_EDGES];
// W pre-split bf16 hi/lo in chunk-interleaved layout:
// word(layer, k2, j) = layer*32768 + (k2>>3)*2048 + j*16 + (k2&3)*4 + ((k2&7)>>2)
// (+2 for lo). Each 2048-word chunk is one contiguous 8KB cp.async.
__device__ uint32_t g_Wc[2 * 32768];

// ---------------- helpers ----------------
#define MMA_BF16(c, a, bb) \
    asm volatile("mma.sync.aligned.m16n8k16.row.col.f32.bf16.bf16.f32 " \
                 "{%0,%1,%2,%3}, {%4,%5,%6,%7}, {%8,%9}, {%0,%1,%2,%3};" \
                 : "+f"((c)[0]), "+f"((c)[1]), "+f"((c)[2]), "+f"((c)[3]) \
                 : "r"((a)[0]), "r"((a)[1]), "r"((a)[2]), "r"((a)[3]), \
                   "r"((bb)[0]), "r"((bb)[1]))

__device__ __forceinline__ uint32_t bf16x2_split_hi(float x0, float x1,
                                                    uint32_t& lo_pack) {
    __nv_bfloat16 h0 = __float2bfloat16(x0);
    __nv_bfloat16 h1 = __float2bfloat16(x1);
    __nv_bfloat16 l0 = __float2bfloat16(x0 - __bfloat162float(h0));
    __nv_bfloat16 l1 = __float2bfloat16(x1 - __bfloat162float(h1));
    lo_pack = (uint32_t)__bfloat16_as_ushort(l0) |
              ((uint32_t)__bfloat16_as_ushort(l1) << 16);
    return (uint32_t)__bfloat16_as_ushort(h0) |
           ((uint32_t)__bfloat16_as_ushort(h1) << 16);
}

__device__ __forceinline__ void cp_async16(void* smem_dst, const void* gsrc) {
    uint32_t d = (uint32_t)__cvta_generic_to_shared(smem_dst);
    asm volatile("cp.async.ca.shared.global [%0], [%1], 16;" :: "r"(d), "l"(gsrc));
}

__device__ __forceinline__ uint32_t pack_h2(float x, float y) {
    __half2 h = __floats2half2_rn(x, y);
    return *reinterpret_cast<uint32_t*>(&h);
}

// ---------------- fused: dst histogram + fp16 conversion + weight pre-split ----------------
__global__ void hist_conv_wsplit_kernel(const int* __restrict__ dst,
                                        const float4* __restrict__ h4,
                                        const float* __restrict__ W0,
                                        const float* __restrict__ W1) {
    int b = blockIdx.x;
    if (b < EDGE_BLOCKS) {
        int e = b * 256 + threadIdx.x;
        if (e < N_EDGES) atomicAdd(&g_cnt[dst[e]], 1);
    } else if (b < EDGE_BLOCKS + CONV_BLOCKS) {
        int i = (b - EDGE_BLOCKS) * 256 + threadIdx.x;   // one float4 -> uint2
        if (i < N_NODES * 32) {
            float4 v = __ldg(h4 + i);
            uint2 o;
            o.x = pack_h2(v.x, v.y);
            o.y = pack_h2(v.z, v.w);
            reinterpret_cast<uint2*>(g_f16)[i] = o;
        }
    } else {
        int i = (b - EDGE_BLOCKS - CONV_BLOCKS) * 256 + threadIdx.x;
        if (i >= 2 * 128 * 128) return;
        int layer = i >> 14;
        int r = i & 16383;
        int k2 = r >> 7, j = r & 127;
        const float* W = layer ? W1 : W0;
        float x0 = W[j * 256 + 2 * k2];
        float x1 = W[j * 256 + 2 * k2 + 1];
        uint32_t lo;
        uint32_t hi = bf16x2_split_hi(x0, x1, lo);
        int wd = layer * 32768 + (k2 >> 3) * 2048 + j * 16 +
                 (k2 & 3) * 4 + ((k2 & 7) >> 2);
        g_Wc[wd]     = hi;
        g_Wc[wd + 2] = lo;
    }
}

// ---------------- CSR offsets (scan-free, warp-aggregated allocator) ----------------
__global__ void offsets_kernel() {
    int i = blockIdx.x * blockDim.x + threadIdx.x;
    int lane = threadIdx.x & 31;
    int c = (i < N_NODES) ? g_cnt[i] : 0;
    int s = c;
#pragma unroll
    for (int off = 1; off < 32; off <<= 1) {
        int v = __shfl_up_sync(0xffffffffu, s, off);
        if (lane >= off) s += v;
    }
    int total = __shfl_sync(0xffffffffu, s, 31);
    int base = 0;
    if (lane == 0) base = atomicAdd(&g_cursor, total);
    base = __shfl_sync(0xffffffffu, base, 0);
    if (i < N_NODES) {
        g_off[i] = base + s - c;
        g_cur[i] = 0;
    }
}

__global__ void scatter_kernel(const int* __restrict__ src,
                               const int* __restrict__ dst,
                               const float* __restrict__ w) {
    int e = blockIdx.x * blockDim.x + threadIdx.x;
    if (e >= N_EDGES) return;
    int d = dst[e];
    int p = g_off[d] + atomicAdd(&g_cur[d], 1);
    g_edge[p] = make_int2(src[e], __float_as_int(w[e]));
}

// ---------------- aggregation: warp per node, fp16 gather, fp32 accumulate ----------------
__global__ __launch_bounds__(256) void agg_csr_kernel() {
    int n = (blockIdx.x * blockDim.x + threadIdx.x) >> 5;
    if (n >= N_NODES) return;
    int lane = threadIdx.x & 31;
    int beg = g_off[n];
    int end = beg + g_cnt[n];
    const uint2* hin16 = reinterpret_cast<const uint2*>(g_f16);

    float4 a0 = make_float4(0.f, 0.f, 0.f, 0.f);
    float4 a1 = make_float4(0.f, 0.f, 0.f, 0.f);
    int e = beg;
    for (; e + 4 <= end; e += 4) {
        int2 e0 = __ldg(g_edge + e);
        int2 e1 = __ldg(g_edge + e + 1);
        int2 e2 = __ldg(g_edge + e + 2);
        int2 e3 = __ldg(g_edge + e + 3);
        uint2 v0 = __ldg(hin16 + (size_t)e0.x * 32 + lane);
        uint2 v1 = __ldg(hin16 + (size_t)e1.x * 32 + lane);
        uint2 v2 = __ldg(hin16 + (size_t)e2.x * 32 + lane);
        uint2 v3 = __ldg(hin16 + (size_t)e3.x * 32 + lane);
        float w0 = __int_as_float(e0.y), w1 = __int_as_float(e1.y);
        float w2 = __int_as_float(e2.y), w3 = __int_as_float(e3.y);
        float2 f0a = __half22float2(*reinterpret_cast<__half2*>(&v0.x));
        float2 f0b = __half22float2(*reinterpret_cast<__half2*>(&v0.y));
        float2 f1a = __half22float2(*reinterpret_cast<__half2*>(&v1.x));
        float2 f1b = __half22float2(*reinterpret_cast<__half2*>(&v1.y));
        float2 f2a = __half22float2(*reinterpret_cast<__half2*>(&v2.x));
        float2 f2b = __half22float2(*reinterpret_cast<__half2*>(&v2.y));
        float2 f3a = __half22float2(*reinterpret_cast<__half2*>(&v3.x));
        float2 f3b = __half22float2(*reinterpret_cast<__half2*>(&v3.y));
        a0.x += w0 * f0a.x; a0.y += w0 * f0a.y; a0.z += w0 * f0b.x; a0.w += w0 * f0b.y;
        a1.x += w1 * f1a.x; a1.y += w1 * f1a.y; a1.z += w1 * f1b.x; a1.w += w1 * f1b.y;
        a0.x += w2 * f2a.x; a0.y += w2 * f2a.y; a0.z += w2 * f2b.x; a0.w += w2 * f2b.y;
        a1.x += w3 * f3a.x; a1.y += w3 * f3a.y; a1.z += w3 * f3b.x; a1.w += w3 * f3b.y;
    }
    for (; e < end; ++e) {
        int2 e0 = __ldg(g_edge + e);
        float w0 = __int_as_float(e0.y);
        uint2 v0 = __ldg(hin16 + (size_t)e0.x * 32 + lane);
        float2 f0a = __half22float2(*reinterpret_cast<__half2*>(&v0.x));
        float2 f0b = __half22float2(*reinterpret_cast<__half2*>(&v0.y));
        a0.x += w0 * f0a.x; a0.y += w0 * f0a.y; a0.z += w0 * f0b.x; a0.w += w0 * f0b.y;
    }
    float inv = (end > beg) ? 1.0f / (float)(end - beg) : 0.0f;
    float4 r = make_float4((a0.x + a1.x) * inv, (a0.y + a1.y) * inv,
                           (a0.z + a1.z) * inv, (a0.w + a1.w) * inv);
    reinterpret_cast<float4*>(g_s)[(size_t)n * 32 + lane] = r;
}

// ---------------- 3xBF16 GEMM (K=256), m16n8k16, 64-row tiles ----------------
// Interleaved smem layouts: one v4 per fragment pair (hi s0, hi s1, lo s0, lo s1).
// A word(m, l2) = m*16 + (l2&3)*4 + (l2>>2)   [+2 lo]   -> frag v4 @ m*16+tig*4
// B word(l2, j) = j*16 + (l2&3)*4 + (l2>>2)   [+2 lo]   -> frag v4 @ j*16+tig*4
#define ASZc 1024                 // words per A buffer (64*16)
#define BSZc 2048                 // words per B buffer (128*16)
#define GEMM_SMEM_BYTES ((2 * ASZc + 2 * BSZc + 64) * 4)

__global__ __launch_bounds__(128, 4) void sage_gemm_bf16(
    const float* __restrict__ hin,   // [N,128] layer input (fp32)
    const float* __restrict__ b,     // [128]
    float* __restrict__ out,         // [N,128]
    int layer, int write16)
{
    extern __shared__ uint32_t smem[];
    uint32_t* AcB = smem;                     // [2][ASZc]
    uint32_t* BcB = AcB + 2 * ASZc;           // [2][BSZc]
    float* norms = reinterpret_cast<float*>(BcB + 2 * BSZc);  // [64]

    const uint32_t* Wc = g_Wc + layer * 32768;

    int t = threadIdx.x;
    int n0 = blockIdx.x * 64;
    int warp = t >> 5, lane = t & 31;
    int col_base = warp * 32;
    int gid = lane >> 2, tig = lane & 3;

    if (t < 64) norms[t] = 0.f;

    float acc[4][4][4];
#pragma unroll
    for (int mt = 0; mt < 4; ++mt)
#pragma unroll
        for (int nt = 0; nt < 4; ++nt)
#pragma unroll
            for (int c = 0; c < 4; ++c) acc[mt][nt][c] = 0.f;

    const float4* hin4 = reinterpret_cast<const float4*>(hin);
    const float4* s4   = reinterpret_cast<const float4*>(g_s);

    int m_[2], f_[2];
#pragma unroll
    for (int i = 0; i < 2; ++i) { int q = t + i * 128; m_[i] = q >> 2; f_[i] = q & 3; }

    auto load_a = [&](int ch, float4 v[2]) {   // ch = chunk index 0..15 (16 k each)
        int kg = ch * 16;
#pragma unroll
        for (int i = 0; i < 2; ++i) {
            int grow = n0 + m_[i];
            v[i] = (kg < 128)
                 ? __ldg(hin4 + (size_t)grow * 32 + (kg >> 2) + f_[i])
                 : __ldg(s4   + (size_t)grow * 32 + ((kg - 128) >> 2) + f_[i]);
        }
    };
    auto store_a = [&](int buf, const float4 v[2]) {
        uint32_t* A = AcB + buf * ASZc;
#pragma unroll
        for (int i = 0; i < 2; ++i) {
            uint32_t l01, l23;
            uint32_t h01 = bf16x2_split_hi(v[i].x, v[i].y, l01);
            uint32_t h23 = bf16x2_split_hi(v[i].z, v[i].w, l23);
            int m = m_[i], f = f_[i];
            int k2a = 2 * f, k2b = 2 * f + 1;
            int wa = m * 16 + (k2a & 3) * 4 + (k2a >> 2);
            int wb = m * 16 + (k2b & 3) * 4 + (k2b >> 2);
            A[wa] = h01; A[wa + 2] = l01;
            A[wb] = h23; A[wb + 2] = l23;
        }
    };
    auto issue_b = [&](int ch, int buf) {
        uint32_t* B = BcB + buf * BSZc;
        const uint32_t* gW = Wc + ch * 2048;
#pragma unroll
        for (int i = 0; i < 4; ++i) {
            int off = t * 4 + i * 512;        // words
            cp_async16(B + off, gW + off);
        }
        asm volatile("cp.async.commit_group;");
    };

    float4 av[2];
    issue_b(0, 0);
    load_a(0, av);
    store_a(0, av);
    asm volatile("cp.async.wait_group 0;");
    __syncthreads();

    for (int kc = 0; kc < 16; ++kc) {
        int cur = kc & 1;
        float4 nav[2];
        if (kc < 15) {
            issue_b(kc + 1, cur ^ 1);
            load_a(kc + 1, nav);
        }

        {
            const uint32_t* Ac = AcB + cur * ASZc;
            const uint32_t* Bc = BcB + cur * BSZc;

            uint32_t bh[4][2], bl[4][2];
#pragma unroll
            for (int nt = 0; nt < 4; ++nt) {
                int j = col_base + nt * 8 + gid;
                uint4 bv = *reinterpret_cast<const uint4*>(Bc + j * 16 + tig * 4);
                bh[nt][0] = bv.x; bh[nt][1] = bv.y;
                bl[nt][0] = bv.z; bl[nt][1] = bv.w;
            }
#pragma unroll
            for (int mt = 0; mt < 4; ++mt) {
                int m = mt * 16 + gid;
                uint4 a0 = *reinterpret_cast<const uint4*>(Ac + m * 16 + tig * 4);
                uint4 a1 = *reinterpret_cast<const uint4*>(Ac + (m + 8) * 16 + tig * 4);
                uint32_t ah[4] = {a0.x, a1.x, a0.y, a1.y};
                uint32_t al[4] = {a0.z, a1.z, a0.w, a1.w};
#pragma unroll
                for (int nt = 0; nt < 4; ++nt) {
                    MMA_BF16(acc[mt][nt], ah, bh[nt]);
                    MMA_BF16(acc[mt][nt], ah, bl[nt]);
                    MMA_BF16(acc[mt][nt], al, bh[nt]);
                }
            }
        }

        if (kc < 15) store_a(cur ^ 1, nav);
        asm volatile("cp.async.wait_group 0;");
        __syncthreads();
    }

    // ---- epilogue: bias + relu + row L2 norm (+ optional fp16 copy) ----
    float2 bias[4];
#pragma unroll
    for (int nt = 0; nt < 4; ++nt)
        bias[nt] = __ldg(reinterpret_cast<const float2*>(b) +
                         (col_base + nt * 8 + 2 * tig) / 2);

#pragma unroll
    for (int mt = 0; mt < 4; ++mt) {
#pragma unroll
        for (int r = 0; r < 2; ++r) {
            float part = 0.f;
#pragma unroll
            for (int nt = 0; nt < 4; ++nt) {
                float y0 = fmaxf(acc[mt][nt][2 * r]     + bias[nt].x, 0.f);
                float y1 = fmaxf(acc[mt][nt][2 * r + 1] + bias[nt].y, 0.f);
                acc[mt][nt][2 * r]     = y0;
                acc[mt][nt][2 * r + 1] = y1;
                part += y0 * y0 + y1 * y1;
            }
            part += __shfl_xor_sync(0xffffffffu, part, 1);
            part += __shfl_xor_sync(0xffffffffu, part, 2);
            if (tig == 0)
                atomicAdd(&norms[mt * 16 + gid + r * 8], part);
        }
    }
    __syncthreads();

#pragma unroll
    for (int mt = 0; mt < 4; ++mt) {
#pragma unroll
        for (int r = 0; r < 2; ++r) {
            int lrow = mt * 16 + gid + r * 8;
            int grow = n0 + lrow;
            float sc = 1.0f / fmaxf(sqrtf(norms[lrow]), 1e-12f);
#pragma unroll
            for (int nt = 0; nt < 4; ++nt) {
                int col = col_base + nt * 8 + 2 * tig;
                float2 o = make_float2(acc[mt][nt][2 * r] * sc,
                                       acc[mt][nt][2 * r + 1] * sc);
                *reinterpret_cast<float2*>(out + (size_t)grow * F + col) = o;
                if (write16)
                    g_f16[(size_t)grow * 64 + (col >> 1)] = pack_h2(o.x, o.y);
            }
        }
    }
}

// ---------------- layer 2a: project h2 -> pself(+bias) [N,16] and pn [N,16] ----------------
// shuffle-based (W accesses coalesced: lane-stride 4B)
__global__ __launch_bounds__(256) void proj32_kernel(
    const float* __restrict__ hin,
    const float* __restrict__ W,     // [16,256]
    const float* __restrict__ b)     // [16]
{
    int n = (blockIdx.x * blockDim.x + threadIdx.x) >> 5;
    if (n >= N_NODES) return;
    int l = threadIdx.x & 31;

    const float* hrow = hin + (size_t)n * F;
    float x[4];
#pragma unroll
    for (int i = 0; i < 4; ++i) x[i] = __ldg(hrow + l + 32 * i);

    float ps[16], pn[16];
#pragma unroll
    for (int j = 0; j < 16; ++j) {
        const float* wrow = W + j * 256;
        float as = 0.f, an = 0.f;
#pragma unroll
        for (int i = 0; i < 4; ++i) {
            as += x[i] * __ldg(wrow + l + 32 * i);
            an += x[i] * __ldg(wrow + 128 + l + 32 * i);
        }
#pragma unroll
        for (int off = 16; off; off >>= 1) {
            as += __shfl_xor_sync(0xffffffffu, as, off);
            an += __shfl_xor_sync(0xffffffffu, an, off);
        }
        ps[j] = as; pn[j] = an;
    }
    if (l < 16) {
        g_h1[(size_t)n * 16 + l] = ps[l] + __ldg(b + l);
        g_s [(size_t)n * 16 + l] = pn[l];
    }
}

// ---------------- layer 2b: 16-dim aggregation + final add (+ state reset) ----------------
__global__ __launch_bounds__(256) void agg16_kernel(float* __restrict__ out) {
    int n = (blockIdx.x * blockDim.x + threadIdx.x) >> 5;
    if (n >= N_NODES) return;
    int lane = threadIdx.x & 31;
    int f = lane & 15, half = lane >> 4;
    int beg = g_off[n];
    int end = beg + g_cnt[n];

    float acc = 0.f;
    for (int e = beg + half; e < end; e += 2) {
        int2 ew = __ldg(g_edge + e);
        float v = __ldg(g_s + (size_t)ew.x * 16 + f);
        acc += __int_as_float(ew.y) * v;
    }
    acc += __shfl_xor_sync(0xffffffffu, acc, 16);

    if (lane < 16) {
        float inv = (end > beg) ? 1.0f / (float)(end - beg) : 0.0f;
        out[(size_t)n * NCLS + f] = g_h1[(size_t)n * 16 + f] + acc * inv;
    }
    // reset counters for the NEXT invocation (statics start zeroed)
    if (lane == 31) g_cnt[n] = 0;
    if (n == 0 && lane == 30) g_cursor = 0;
}

// ---------------- launch ----------------
extern "C" void kernel_launch(void* const* d_in, const int* in_sizes, int n_in,
                              void* d_out, int out_size) {
    const float* h  = (const float*)d_in[0];
    const float* w  = (const float*)d_in[1];
    const int* src  = (const int*)d_in[2];
    const int* dst  = (const int*)d_in[3];
    const float* W0 = (const float*)d_in[4];
    const float* b0 = (const float*)d_in[5];
    const float* W1 = (const float*)d_in[6];
    const float* b1 = (const float*)d_in[7];
    const float* W2 = (const float*)d_in[8];
    const float* b2 = (const float*)d_in[9];
    float* out = (float*)d_out;

    void *ph1 = nullptr, *ph2 = nullptr;
    cudaGetSymbolAddress(&ph1, g_h1);
    cudaGetSymbolAddress(&ph2, g_h2);
    float* h1 = (float*)ph1;
    float* h2 = (float*)ph2;

    cudaFuncSetAttribute(sage_gemm_bf16,
                         cudaFuncAttributeMaxDynamicSharedMemorySize,
                         GEMM_SMEM_BYTES);

    const int NODE_BLOCKS  = (N_NODES + 255) / 256;            // 157
    const int WARPN_BLOCKS = (N_NODES * 32 + 255) / 256;       // 5000
    const int GEMM_BLOCKS  = (N_NODES + 63) / 64;              // 625

    // CSR build + fp16 conversion + weight pre-split (one fused launch + 2)
    hist_conv_wsplit_kernel<<<EDGE_BLOCKS + CONV_BLOCKS + WSP_BLOCKS, 256>>>(
        dst, (const float4*)h, W0, W1);
    offsets_kernel<<<NODE_BLOCKS, 256>>>();
    scatter_kernel<<<EDGE_BLOCKS, 256>>>(src, dst, w);

    // layer 0 (gemm also emits fp16 h1 into g_f16 for layer-1 agg)
    agg_csr_kernel<<<WARPN_BLOCKS, 256>>>();
    sage_gemm_bf16<<<GEMM_BLOCKS, 128, GEMM_SMEM_BYTES>>>(h, b0, h1, 0, 1);

    // layer 1
    agg_csr_kernel<<<WARPN_BLOCKS, 256>>>();
    sage_gemm_bf16<<<GEMM_BLOCKS, 128, GEMM_SMEM_BYTES>>>(h1, b1, h2, 1, 0);

    // layer 2: project first (linearity), then 16-dim aggregate
    proj32_kernel<<<WARPN_BLOCKS, 256>>>(h2, W2, b2);
    agg16_kernel<<<WARPN_BLOCKS, 256>>>(out);
}

// round 16
// speedup vs baseline: 1.0226x; 1.0226x over previous
#include <cuda_runtime.h>
#include <cuda_bf16.h>
#include <cuda_fp16.h>
#include <math.h>
#include <stdint.h>

#define N_NODES 40000
#define N_EDGES 640000
#define F 128
#define NCLS 16

#define EDGE_BLOCKS 2500          // ceil(640000/256)
#define CONV_BLOCKS 5000          // N_NODES*32 float4-quads / 256
#define WSP_BLOCKS 128            // 2*128*128 packed pairs / 256

// ---------------- scratch (no allocations allowed) ----------------
// g_cnt/g_cursor are zero at module load; agg16_kernel (last kernel of every
// call) re-zeroes them, so every invocation sees zeros.
__device__ float g_s[N_NODES * F];       // aggregation result / layer-2 pn
__device__ float g_h1[N_NODES * F];      // layer-0 output / layer-2 pself
__device__ float g_h2[N_NODES * F];      // layer-1 output
__device__ uint32_t g_f16[N_NODES * 64]; // fp16 copy of current agg input (half2)
__device__ int   g_cnt[N_NODES];
__device__ int   g_cur[N_NODES];
__device__ int   g_off[N_NODES];
__device__ int   g_cursor;
__device__ int2  g_edge[N_EDGES];
// W pre-split bf16 hi/lo, chunk-interleaved:
// word(layer,k2,j) = layer*32768 + (k2>>3)*2048 + j*16 + (k2&3)*4 + ((k2&7)>>2)
// (+2 for lo). Each 2048-word chunk (16 k) is one contiguous 8KB cp.async;
// B fragment = one uint4 at j*16 + tig*4 = {hi_s0, hi_s1, lo_s0, lo_s1}.
__device__ uint32_t g_Wc[2 * 32768];

// ---------------- helpers ----------------
#define MMA_BF16(c, a, bb) \
    asm volatile("mma.sync.aligned.m16n8k16.row.col.f32.bf16.bf16.f32 " \
                 "{%0,%1,%2,%3}, {%4,%5,%6,%7}, {%8,%9}, {%0,%1,%2,%3};" \
                 : "+f"((c)[0]), "+f"((c)[1]), "+f"((c)[2]), "+f"((c)[3]) \
                 : "r"((a)[0]), "r"((a)[1]), "r"((a)[2]), "r"((a)[3]), \
                   "r"((bb)[0]), "r"((bb)[1]))

__device__ __forceinline__ uint32_t bf16x2_split_hi(float x0, float x1,
                                                    uint32_t& lo_pack) {
    __nv_bfloat16 h0 = __float2bfloat16(x0);
    __nv_bfloat16 h1 = __float2bfloat16(x1);
    __nv_bfloat16 l0 = __float2bfloat16(x0 - __bfloat162float(h0));
    __nv_bfloat16 l1 = __float2bfloat16(x1 - __bfloat162float(h1));
    lo_pack = (uint32_t)__bfloat16_as_ushort(l0) |
              ((uint32_t)__bfloat16_as_ushort(l1) << 16);
    return (uint32_t)__bfloat16_as_ushort(h0) |
           ((uint32_t)__bfloat16_as_ushort(h1) << 16);
}

__device__ __forceinline__ void cp_async16(void* smem_dst, const void* gsrc) {
    uint32_t d = (uint32_t)__cvta_generic_to_shared(smem_dst);
    asm volatile("cp.async.ca.shared.global [%0], [%1], 16;" :: "r"(d), "l"(gsrc));
}

__device__ __forceinline__ uint32_t pack_h2(float x, float y) {
    __half2 h = __floats2half2_rn(x, y);
    return *reinterpret_cast<uint32_t*>(&h);
}

// ---------------- fused: dst histogram + fp16 conversion + weight pre-split ----------------
__global__ void hist_conv_wsplit_kernel(const int* __restrict__ dst,
                                        const float4* __restrict__ h4,
                                        const float* __restrict__ W0,
                                        const float* __restrict__ W1) {
    int b = blockIdx.x;
    if (b < EDGE_BLOCKS) {
        int e = b * 256 + threadIdx.x;
        if (e < N_EDGES) atomicAdd(&g_cnt[dst[e]], 1);
    } else if (b < EDGE_BLOCKS + CONV_BLOCKS) {
        int i = (b - EDGE_BLOCKS) * 256 + threadIdx.x;   // one float4 -> uint2
        if (i < N_NODES * 32) {
            float4 v = __ldg(h4 + i);
            uint2 o;
            o.x = pack_h2(v.x, v.y);
            o.y = pack_h2(v.z, v.w);
            reinterpret_cast<uint2*>(g_f16)[i] = o;
        }
    } else {
        int i = (b - EDGE_BLOCKS - CONV_BLOCKS) * 256 + threadIdx.x;
        if (i >= 2 * 128 * 128) return;
        int layer = i >> 14;
        int r = i & 16383;
        int k2 = r >> 7, j = r & 127;
        const float* W = layer ? W1 : W0;
        float x0 = W[j * 256 + 2 * k2];
        float x1 = W[j * 256 + 2 * k2 + 1];
        uint32_t lo;
        uint32_t hi = bf16x2_split_hi(x0, x1, lo);
        int wd = layer * 32768 + (k2 >> 3) * 2048 + j * 16 +
                 (k2 & 3) * 4 + ((k2 & 7) >> 2);
        g_Wc[wd]     = hi;
        g_Wc[wd + 2] = lo;
    }
}

// ---------------- CSR offsets (scan-free, warp-aggregated allocator) ----------------
__global__ void offsets_kernel() {
    int i = blockIdx.x * blockDim.x + threadIdx.x;
    int lane = threadIdx.x & 31;
    int c = (i < N_NODES) ? g_cnt[i] : 0;
    int s = c;
#pragma unroll
    for (int off = 1; off < 32; off <<= 1) {
        int v = __shfl_up_sync(0xffffffffu, s, off);
        if (lane >= off) s += v;
    }
    int total = __shfl_sync(0xffffffffu, s, 31);
    int base = 0;
    if (lane == 0) base = atomicAdd(&g_cursor, total);
    base = __shfl_sync(0xffffffffu, base, 0);
    if (i < N_NODES) {
        g_off[i] = base + s - c;
        g_cur[i] = 0;
    }
}

__global__ void scatter_kernel(const int* __restrict__ src,
                               const int* __restrict__ dst,
                               const float* __restrict__ w) {
    int e = blockIdx.x * blockDim.x + threadIdx.x;
    if (e >= N_EDGES) return;
    int d = dst[e];
    int p = g_off[d] + atomicAdd(&g_cur[d], 1);
    g_edge[p] = make_int2(src[e], __float_as_int(w[e]));
}

// ---------------- aggregation: warp per node, fp16 gather, fp32 accumulate ----------------
__global__ __launch_bounds__(256) void agg_csr_kernel() {
    int n = (blockIdx.x * blockDim.x + threadIdx.x) >> 5;
    if (n >= N_NODES) return;
    int lane = threadIdx.x & 31;
    int beg = g_off[n];
    int end = beg + g_cnt[n];
    const uint2* hin16 = reinterpret_cast<const uint2*>(g_f16);

    float4 a0 = make_float4(0.f, 0.f, 0.f, 0.f);
    float4 a1 = make_float4(0.f, 0.f, 0.f, 0.f);
    int e = beg;
    for (; e + 4 <= end; e += 4) {
        int2 e0 = __ldg(g_edge + e);
        int2 e1 = __ldg(g_edge + e + 1);
        int2 e2 = __ldg(g_edge + e + 2);
        int2 e3 = __ldg(g_edge + e + 3);
        uint2 v0 = __ldg(hin16 + (size_t)e0.x * 32 + lane);
        uint2 v1 = __ldg(hin16 + (size_t)e1.x * 32 + lane);
        uint2 v2 = __ldg(hin16 + (size_t)e2.x * 32 + lane);
        uint2 v3 = __ldg(hin16 + (size_t)e3.x * 32 + lane);
        float w0 = __int_as_float(e0.y), w1 = __int_as_float(e1.y);
        float w2 = __int_as_float(e2.y), w3 = __int_as_float(e3.y);
        float2 f0a = __half22float2(*reinterpret_cast<__half2*>(&v0.x));
        float2 f0b = __half22float2(*reinterpret_cast<__half2*>(&v0.y));
        float2 f1a = __half22float2(*reinterpret_cast<__half2*>(&v1.x));
        float2 f1b = __half22float2(*reinterpret_cast<__half2*>(&v1.y));
        float2 f2a = __half22float2(*reinterpret_cast<__half2*>(&v2.x));
        float2 f2b = __half22float2(*reinterpret_cast<__half2*>(&v2.y));
        float2 f3a = __half22float2(*reinterpret_cast<__half2*>(&v3.x));
        float2 f3b = __half22float2(*reinterpret_cast<__half2*>(&v3.y));
        a0.x += w0 * f0a.x; a0.y += w0 * f0a.y; a0.z += w0 * f0b.x; a0.w += w0 * f0b.y;
        a1.x += w1 * f1a.x; a1.y += w1 * f1a.y; a1.z += w1 * f1b.x; a1.w += w1 * f1b.y;
        a0.x += w2 * f2a.x; a0.y += w2 * f2a.y; a0.z += w2 * f2b.x; a0.w += w2 * f2b.y;
        a1.x += w3 * f3a.x; a1.y += w3 * f3a.y; a1.z += w3 * f3b.x; a1.w += w3 * f3b.y;
    }
    for (; e < end; ++e) {
        int2 e0 = __ldg(g_edge + e);
        float w0 = __int_as_float(e0.y);
        uint2 v0 = __ldg(hin16 + (size_t)e0.x * 32 + lane);
        float2 f0a = __half22float2(*reinterpret_cast<__half2*>(&v0.x));
        float2 f0b = __half22float2(*reinterpret_cast<__half2*>(&v0.y));
        a0.x += w0 * f0a.x; a0.y += w0 * f0a.y; a0.z += w0 * f0b.x; a0.w += w0 * f0b.y;
    }
    float inv = (end > beg) ? 1.0f / (float)(end - beg) : 0.0f;
    float4 r = make_float4((a0.x + a1.x) * inv, (a0.y + a1.y) * inv,
                           (a0.z + a1.z) * inv, (a0.w + a1.w) * inv);
    reinterpret_cast<float4*>(g_s)[(size_t)n * 32 + lane] = r;
}

// ---------------- 3xBF16 GEMM (K=256), m16n8k16, 64-row tiles ----------------
// A smem: packed bf16x2 [m][k2] stride 12 (R14 layout, frag LDS conflict-free).
// B smem: chunk-interleaved (R15 layout): frag = one uint4 @ j*16 + tig*4.
#define ASZ (64 * 12)             // uint32 per A buffer
#define BSZc 2048                 // uint32 per B buffer (one 16-k chunk)
#define GEMM_SMEM_BYTES ((4 * ASZ + 2 * BSZc + 64) * 4)

__global__ __launch_bounds__(128, 4) void sage_gemm_bf16(
    const float* __restrict__ hin,   // [N,128] layer input (fp32)
    const float* __restrict__ b,     // [128]
    float* __restrict__ out,         // [N,128]
    int layer, int write16)
{
    extern __shared__ uint32_t smem[];
    uint32_t* AhB = smem;                     // [2][ASZ]
    uint32_t* AlB = AhB + 2 * ASZ;
    uint32_t* BcB = AlB + 2 * ASZ;            // [2][BSZc]
    float* norms = reinterpret_cast<float*>(BcB + 2 * BSZc);  // [64]

    const uint32_t* Wc = g_Wc + layer * 32768;

    int t = threadIdx.x;
    int n0 = blockIdx.x * 64;
    int warp = t >> 5, lane = t & 31;
    int col_base = warp * 32;
    int gid = lane >> 2, tig = lane & 3;

    if (t < 64) norms[t] = 0.f;

    float acc[4][4][4];
#pragma unroll
    for (int mt = 0; mt < 4; ++mt)
#pragma unroll
        for (int nt = 0; nt < 4; ++nt)
#pragma unroll
            for (int c = 0; c < 4; ++c) acc[mt][nt][c] = 0.f;

    const float4* hin4 = reinterpret_cast<const float4*>(hin);
    const float4* s4   = reinterpret_cast<const float4*>(g_s);

    int m_[2], f_[2];
#pragma unroll
    for (int i = 0; i < 2; ++i) { int q = t + i * 128; m_[i] = q >> 2; f_[i] = q & 3; }

    auto load_a = [&](int ch, float4 v[2]) {   // ch = chunk 0..15 (16 k each)
        int kg = ch * 16;
#pragma unroll
        for (int i = 0; i < 2; ++i) {
            int grow = n0 + m_[i];
            v[i] = (kg < 128)
                 ? __ldg(hin4 + (size_t)grow * 32 + (kg >> 2) + f_[i])
                 : __ldg(s4   + (size_t)grow * 32 + ((kg - 128) >> 2) + f_[i]);
        }
    };
    auto store_a = [&](int buf, const float4 v[2]) {
        uint32_t* Ah = AhB + buf * ASZ;
        uint32_t* Al = AlB + buf * ASZ;
#pragma unroll
        for (int i = 0; i < 2; ++i) {
            uint32_t l01, l23;
            uint32_t h01 = bf16x2_split_hi(v[i].x, v[i].y, l01);
            uint32_t h23 = bf16x2_split_hi(v[i].z, v[i].w, l23);
            int base = m_[i] * 12 + f_[i] * 2;
            Ah[base] = h01; Ah[base + 1] = h23;
            Al[base] = l01; Al[base + 1] = l23;
        }
    };
    auto issue_b = [&](int ch, int buf) {
        uint32_t* B = BcB + buf * BSZc;
        const uint32_t* gW = Wc + ch * 2048;
#pragma unroll
        for (int i = 0; i < 4; ++i) {
            int off = t * 4 + i * 512;        // words
            cp_async16(B + off, gW + off);
        }
        asm volatile("cp.async.commit_group;");
    };

    float4 av[2];
    issue_b(0, 0);
    load_a(0, av);
    store_a(0, av);
    asm volatile("cp.async.wait_group 0;");
    __syncthreads();

    for (int kc = 0; kc < 16; ++kc) {
        int cur = kc & 1;
        float4 nav[2];
        if (kc < 15) {
            issue_b(kc + 1, cur ^ 1);
            load_a(kc + 1, nav);
        }

        {
            const uint32_t* Ah = AhB + cur * ASZ;
            const uint32_t* Al = AlB + cur * ASZ;
            const uint32_t* Bc = BcB + cur * BSZc;

            uint32_t bh[4][2], bl[4][2];
#pragma unroll
            for (int nt = 0; nt < 4; ++nt) {
                int j = col_base + nt * 8 + gid;
                uint4 bv = *reinterpret_cast<const uint4*>(Bc + j * 16 + tig * 4);
                bh[nt][0] = bv.x; bh[nt][1] = bv.y;
                bl[nt][0] = bv.z; bl[nt][1] = bv.w;
            }
#pragma unroll
            for (int mt = 0; mt < 4; ++mt) {
                int m = mt * 16 + gid;
                uint32_t ah[4], al[4];
                ah[0] = Ah[m * 12 + tig];
                ah[1] = Ah[(m + 8) * 12 + tig];
                ah[2] = Ah[m * 12 + tig + 4];
                ah[3] = Ah[(m + 8) * 12 + tig + 4];
                al[0] = Al[m * 12 + tig];
                al[1] = Al[(m + 8) * 12 + tig];
                al[2] = Al[m * 12 + tig + 4];
                al[3] = Al[(m + 8) * 12 + tig + 4];
#pragma unroll
                for (int nt = 0; nt < 4; ++nt) {
                    MMA_BF16(acc[mt][nt], ah, bh[nt]);
                    MMA_BF16(acc[mt][nt], ah, bl[nt]);
                    MMA_BF16(acc[mt][nt], al, bh[nt]);
                }
            }
        }

        if (kc < 15) store_a(cur ^ 1, nav);
        asm volatile("cp.async.wait_group 0;");
        __syncthreads();
    }

    // ---- epilogue: bias + relu + row L2 norm (+ optional fp16 copy) ----
    float2 bias[4];
#pragma unroll
    for (int nt = 0; nt < 4; ++nt)
        bias[nt] = __ldg(reinterpret_cast<const float2*>(b) +
                         (col_base + nt * 8 + 2 * tig) / 2);

#pragma unroll
    for (int mt = 0; mt < 4; ++mt) {
#pragma unroll
        for (int r = 0; r < 2; ++r) {
            float part = 0.f;
#pragma unroll
            for (int nt = 0; nt < 4; ++nt) {
                float y0 = fmaxf(acc[mt][nt][2 * r]     + bias[nt].x, 0.f);
                float y1 = fmaxf(acc[mt][nt][2 * r + 1] + bias[nt].y, 0.f);
                acc[mt][nt][2 * r]     = y0;
                acc[mt][nt][2 * r + 1] = y1;
                part += y0 * y0 + y1 * y1;
            }
            part += __shfl_xor_sync(0xffffffffu, part, 1);
            part += __shfl_xor_sync(0xffffffffu, part, 2);
            if (tig == 0)
                atomicAdd(&norms[mt * 16 + gid + r * 8], part);
        }
    }
    __syncthreads();

#pragma unroll
    for (int mt = 0; mt < 4; ++mt) {
#pragma unroll
        for (int r = 0; r < 2; ++r) {
            int lrow = mt * 16 + gid + r * 8;
            int grow = n0 + lrow;
            float sc = 1.0f / fmaxf(sqrtf(norms[lrow]), 1e-12f);
#pragma unroll
            for (int nt = 0; nt < 4; ++nt) {
                int col = col_base + nt * 8 + 2 * tig;
                float2 o = make_float2(acc[mt][nt][2 * r] * sc,
                                       acc[mt][nt][2 * r + 1] * sc);
                *reinterpret_cast<float2*>(out + (size_t)grow * F + col) = o;
                if (write16)
                    g_f16[(size_t)grow * 64 + (col >> 1)] = pack_h2(o.x, o.y);
            }
        }
    }
}

// ---------------- layer 2a: project h2 -> pself(+bias) [N,16] and pn [N,16] ----------------
// shuffle-based (W accesses coalesced: lane-stride 4B)
__global__ __launch_bounds__(256) void proj32_kernel(
    const float* __restrict__ hin,
    const float* __restrict__ W,     // [16,256]
    const float* __restrict__ b)     // [16]
{
    int n = (blockIdx.x * blockDim.x + threadIdx.x) >> 5;
    if (n >= N_NODES) return;
    int l = threadIdx.x & 31;

    const float* hrow = hin + (size_t)n * F;
    float x[4];
#pragma unroll
    for (int i = 0; i < 4; ++i) x[i] = __ldg(hrow + l + 32 * i);

    float ps[16], pn[16];
#pragma unroll
    for (int j = 0; j < 16; ++j) {
        const float* wrow = W + j * 256;
        float as = 0.f, an = 0.f;
#pragma unroll
        for (int i = 0; i < 4; ++i) {
            as += x[i] * __ldg(wrow + l + 32 * i);
            an += x[i] * __ldg(wrow + 128 + l + 32 * i);
        }
#pragma unroll
        for (int off = 16; off; off >>= 1) {
            as += __shfl_xor_sync(0xffffffffu, as, off);
            an += __shfl_xor_sync(0xffffffffu, an, off);
        }
        ps[j] = as; pn[j] = an;
    }
    if (l < 16) {
        g_h1[(size_t)n * 16 + l] = ps[l] + __ldg(b + l);
        g_s [(size_t)n * 16 + l] = pn[l];
    }
}

// ---------------- layer 2b: 16-dim aggregation + final add (+ state reset) ----------------
__global__ __launch_bounds__(256) void agg16_kernel(float* __restrict__ out) {
    int n = (blockIdx.x * blockDim.x + threadIdx.x) >> 5;
    if (n >= N_NODES) return;
    int lane = threadIdx.x & 31;
    int f = lane & 15, half = lane >> 4;
    int beg = g_off[n];
    int end = beg + g_cnt[n];

    float acc = 0.f;
    for (int e = beg + half; e < end; e += 2) {
        int2 ew = __ldg(g_edge + e);
        float v = __ldg(g_s + (size_t)ew.x * 16 + f);
        acc += __int_as_float(ew.y) * v;
    }
    acc += __shfl_xor_sync(0xffffffffu, acc, 16);

    if (lane < 16) {
        float inv = (end > beg) ? 1.0f / (float)(end - beg) : 0.0f;
        out[(size_t)n * NCLS + f] = g_h1[(size_t)n * 16 + f] + acc * inv;
    }
    // reset counters for the NEXT invocation (statics start zeroed)
    if (lane == 31) g_cnt[n] = 0;
    if (n == 0 && lane == 30) g_cursor = 0;
}

// ---------------- launch ----------------
extern "C" void kernel_launch(void* const* d_in, const int* in_sizes, int n_in,
                              void* d_out, int out_size) {
    const float* h  = (const float*)d_in[0];
    const float* w  = (const float*)d_in[1];
    const int* src  = (const int*)d_in[2];
    const int* dst  = (const int*)d_in[3];
    const float* W0 = (const float*)d_in[4];
    const float* b0 = (const float*)d_in[5];
    const float* W1 = (const float*)d_in[6];
    const float* b1 = (const float*)d_in[7];
    const float* W2 = (const float*)d_in[8];
    const float* b2 = (const float*)d_in[9];
    float* out = (float*)d_out;

    void *ph1 = nullptr, *ph2 = nullptr;
    cudaGetSymbolAddress(&ph1, g_h1);
    cudaGetSymbolAddress(&ph2, g_h2);
    float* h1 = (float*)ph1;
    float* h2 = (float*)ph2;

    cudaFuncSetAttribute(sage_gemm_bf16,
                         cudaFuncAttributeMaxDynamicSharedMemorySize,
                         GEMM_SMEM_BYTES);

    const int NODE_BLOCKS  = (N_NODES + 255) / 256;            // 157
    const int WARPN_BLOCKS = (N_NODES * 32 + 255) / 256;       // 5000
    const int GEMM_BLOCKS  = (N_NODES + 63) / 64;              // 625

    // CSR build + fp16 conversion + weight pre-split (one fused launch + 2)
    hist_conv_wsplit_kernel<<<EDGE_BLOCKS + CONV_BLOCKS + WSP_BLOCKS, 256>>>(
        dst, (const float4*)h, W0, W1);
    offsets_kernel<<<NODE_BLOCKS, 256>>>();
    scatter_kernel<<<EDGE_BLOCKS, 256>>>(src, dst, w);

    // layer 0 (gemm also emits fp16 h1 into g_f16 for layer-1 agg)
    agg_csr_kernel<<<WARPN_BLOCKS, 256>>>();
    sage_gemm_bf16<<<GEMM_BLOCKS, 128, GEMM_SMEM_BYTES>>>(h, b0, h1, 0, 1);

    // layer 1
    agg_csr_kernel<<<WARPN_BLOCKS, 256>>>();
    sage_gemm_bf16<<<GEMM_BLOCKS, 128, GEMM_SMEM_BYTES>>>(h1, b1, h2, 1, 0);

    // layer 2: project first (linearity), then 16-dim aggregate
    proj32_kernel<<<WARPN_BLOCKS, 256>>>(h2, W2, b2);
    agg16_kernel<<<WARPN_BLOCKS, 256>>>(out);
}

// round 17
// speedup vs baseline: 1.0623x; 1.0388x over previous
#include <cuda_runtime.h>
#include <cuda_bf16.h>
#include <cuda_fp16.h>
#include <math.h>
#include <stdint.h>

#define N_NODES 40000
#define N_EDGES 640000
#define F 128
#define NCLS 16

#define EDGE_BLOCKS 2500          // ceil(640000/256)
#define CONV_BLOCKS 5000          // N_NODES*32 float4-quads / 256
#define WSP_BLOCKS 128            // 2*128*128 packed pairs / 256

// ---------------- scratch (no allocations allowed) ----------------
// g_cnt/g_cursor are zero at module load; agg16_kernel (last kernel of every
// call) re-zeroes them, so every invocation sees zeros.
__device__ float g_s[N_NODES * F];       // aggregation result / layer-2 pn (fp16 packed)
__device__ float g_h1[N_NODES * F];      // layer-0 output / layer-2 pself
__device__ float g_h2[N_NODES * F];      // layer-1 output
__device__ uint32_t g_f16[N_NODES * 64]; // fp16 copy of current agg input (half2)
__device__ int   g_cnt[N_NODES];
__device__ int   g_cur[N_NODES];
__device__ int   g_off[N_NODES];
__device__ int   g_cursor;
__device__ int2  g_edge[N_EDGES];
// W pre-split bf16 hi/lo, chunk-interleaved:
// word(layer,k2,j) = layer*32768 + (k2>>3)*2048 + j*16 + (k2&3)*4 + ((k2&7)>>2)
// (+2 for lo). Each 2048-word chunk (16 k) is one contiguous 8KB cp.async;
// B fragment = one uint4 at j*16 + tig*4 = {hi_s0, hi_s1, lo_s0, lo_s1}.
__device__ uint32_t g_Wc[2 * 32768];

// ---------------- helpers ----------------
#define MMA_BF16(c, a, bb) \
    asm volatile("mma.sync.aligned.m16n8k16.row.col.f32.bf16.bf16.f32 " \
                 "{%0,%1,%2,%3}, {%4,%5,%6,%7}, {%8,%9}, {%0,%1,%2,%3};" \
                 : "+f"((c)[0]), "+f"((c)[1]), "+f"((c)[2]), "+f"((c)[3]) \
                 : "r"((a)[0]), "r"((a)[1]), "r"((a)[2]), "r"((a)[3]), \
                   "r"((bb)[0]), "r"((bb)[1]))

__device__ __forceinline__ uint32_t bf16x2_split_hi(float x0, float x1,
                                                    uint32_t& lo_pack) {
    __nv_bfloat16 h0 = __float2bfloat16(x0);
    __nv_bfloat16 h1 = __float2bfloat16(x1);
    __nv_bfloat16 l0 = __float2bfloat16(x0 - __bfloat162float(h0));
    __nv_bfloat16 l1 = __float2bfloat16(x1 - __bfloat162float(h1));
    lo_pack = (uint32_t)__bfloat16_as_ushort(l0) |
              ((uint32_t)__bfloat16_as_ushort(l1) << 16);
    return (uint32_t)__bfloat16_as_ushort(h0) |
           ((uint32_t)__bfloat16_as_ushort(h1) << 16);
}

__device__ __forceinline__ void cp_async16(void* smem_dst, const void* gsrc) {
    uint32_t d = (uint32_t)__cvta_generic_to_shared(smem_dst);
    asm volatile("cp.async.ca.shared.global [%0], [%1], 16;" :: "r"(d), "l"(gsrc));
}

__device__ __forceinline__ uint32_t pack_h2(float x, float y) {
    __half2 h = __floats2half2_rn(x, y);
    return *reinterpret_cast<uint32_t*>(&h);
}

__device__ __forceinline__ float2 unpack_h2(uint32_t v) {
    return __half22float2(*reinterpret_cast<__half2*>(&v));
}

// ---------------- fused: dst histogram + fp16 conversion + weight pre-split ----------------
__global__ void hist_conv_wsplit_kernel(const int* __restrict__ dst,
                                        const float4* __restrict__ h4,
                                        const float* __restrict__ W0,
                                        const float* __restrict__ W1) {
    int b = blockIdx.x;
    if (b < EDGE_BLOCKS) {
        int e = b * 256 + threadIdx.x;
        if (e < N_EDGES) atomicAdd(&g_cnt[dst[e]], 1);
    } else if (b < EDGE_BLOCKS + CONV_BLOCKS) {
        int i = (b - EDGE_BLOCKS) * 256 + threadIdx.x;   // one float4 -> uint2
        if (i < N_NODES * 32) {
            float4 v = __ldg(h4 + i);
            uint2 o;
            o.x = pack_h2(v.x, v.y);
            o.y = pack_h2(v.z, v.w);
            reinterpret_cast<uint2*>(g_f16)[i] = o;
        }
    } else {
        int i = (b - EDGE_BLOCKS - CONV_BLOCKS) * 256 + threadIdx.x;
        if (i >= 2 * 128 * 128) return;
        int layer = i >> 14;
        int r = i & 16383;
        int k2 = r >> 7, j = r & 127;
        const float* W = layer ? W1 : W0;
        float x0 = W[j * 256 + 2 * k2];
        float x1 = W[j * 256 + 2 * k2 + 1];
        uint32_t lo;
        uint32_t hi = bf16x2_split_hi(x0, x1, lo);
        int wd = layer * 32768 + (k2 >> 3) * 2048 + j * 16 +
                 (k2 & 3) * 4 + ((k2 & 7) >> 2);
        g_Wc[wd]     = hi;
        g_Wc[wd + 2] = lo;
    }
}

// ---------------- CSR offsets (scan-free, warp-aggregated allocator) ----------------
__global__ void offsets_kernel() {
    int i = blockIdx.x * blockDim.x + threadIdx.x;
    int lane = threadIdx.x & 31;
    int c = (i < N_NODES) ? g_cnt[i] : 0;
    int s = c;
#pragma unroll
    for (int off = 1; off < 32; off <<= 1) {
        int v = __shfl_up_sync(0xffffffffu, s, off);
        if (lane >= off) s += v;
    }
    int total = __shfl_sync(0xffffffffu, s, 31);
    int base = 0;
    if (lane == 0) base = atomicAdd(&g_cursor, total);
    base = __shfl_sync(0xffffffffu, base, 0);
    if (i < N_NODES) {
        g_off[i] = base + s - c;
        g_cur[i] = 0;
    }
}

__global__ void scatter_kernel(const int* __restrict__ src,
                               const int* __restrict__ dst,
                               const float* __restrict__ w) {
    int e = blockIdx.x * blockDim.x + threadIdx.x;
    if (e >= N_EDGES) return;
    int d = dst[e];
    int p = g_off[d] + atomicAdd(&g_cur[d], 1);
    g_edge[p] = make_int2(src[e], __float_as_int(w[e]));
}

// ---------------- aggregation: warp per node, fp16 gather, fp32 accumulate ----------------
__global__ __launch_bounds__(256) void agg_csr_kernel() {
    int n = (blockIdx.x * blockDim.x + threadIdx.x) >> 5;
    if (n >= N_NODES) return;
    int lane = threadIdx.x & 31;
    int beg = g_off[n];
    int end = beg + g_cnt[n];
    const uint2* hin16 = reinterpret_cast<const uint2*>(g_f16);

    float4 a0 = make_float4(0.f, 0.f, 0.f, 0.f);
    float4 a1 = make_float4(0.f, 0.f, 0.f, 0.f);
    int e = beg;
    for (; e + 4 <= end; e += 4) {
        int2 e0 = __ldg(g_edge + e);
        int2 e1 = __ldg(g_edge + e + 1);
        int2 e2 = __ldg(g_edge + e + 2);
        int2 e3 = __ldg(g_edge + e + 3);
        uint2 v0 = __ldg(hin16 + (size_t)e0.x * 32 + lane);
        uint2 v1 = __ldg(hin16 + (size_t)e1.x * 32 + lane);
        uint2 v2 = __ldg(hin16 + (size_t)e2.x * 32 + lane);
        uint2 v3 = __ldg(hin16 + (size_t)e3.x * 32 + lane);
        float w0 = __int_as_float(e0.y), w1 = __int_as_float(e1.y);
        float w2 = __int_as_float(e2.y), w3 = __int_as_float(e3.y);
        float2 f0a = unpack_h2(v0.x), f0b = unpack_h2(v0.y);
        float2 f1a = unpack_h2(v1.x), f1b = unpack_h2(v1.y);
        float2 f2a = unpack_h2(v2.x), f2b = unpack_h2(v2.y);
        float2 f3a = unpack_h2(v3.x), f3b = unpack_h2(v3.y);
        a0.x += w0 * f0a.x; a0.y += w0 * f0a.y; a0.z += w0 * f0b.x; a0.w += w0 * f0b.y;
        a1.x += w1 * f1a.x; a1.y += w1 * f1a.y; a1.z += w1 * f1b.x; a1.w += w1 * f1b.y;
        a0.x += w2 * f2a.x; a0.y += w2 * f2a.y; a0.z += w2 * f2b.x; a0.w += w2 * f2b.y;
        a1.x += w3 * f3a.x; a1.y += w3 * f3a.y; a1.z += w3 * f3b.x; a1.w += w3 * f3b.y;
    }
    for (; e < end; ++e) {
        int2 e0 = __ldg(g_edge + e);
        float w0 = __int_as_float(e0.y);
        uint2 v0 = __ldg(hin16 + (size_t)e0.x * 32 + lane);
        float2 f0a = unpack_h2(v0.x), f0b = unpack_h2(v0.y);
        a0.x += w0 * f0a.x; a0.y += w0 * f0a.y; a0.z += w0 * f0b.x; a0.w += w0 * f0b.y;
    }
    float inv = (end > beg) ? 1.0f / (float)(end - beg) : 0.0f;
    float4 r = make_float4((a0.x + a1.x) * inv, (a0.y + a1.y) * inv,
                           (a0.z + a1.z) * inv, (a0.w + a1.w) * inv);
    reinterpret_cast<float4*>(g_s)[(size_t)n * 32 + lane] = r;
}

// ---------------- 3xBF16 GEMM (K=256), m16n8k16, 64-row tiles ----------------
#define ASZ (64 * 12)             // uint32 per A buffer
#define BSZc 2048                 // uint32 per B buffer (one 16-k chunk)
#define GEMM_SMEM_BYTES ((4 * ASZ + 2 * BSZc + 64) * 4)

__global__ __launch_bounds__(128, 4) void sage_gemm_bf16(
    const float* __restrict__ hin,   // [N,128] layer input (fp32)
    const float* __restrict__ b,     // [128]
    float* __restrict__ out,         // [N,128]
    int layer, int write16)
{
    extern __shared__ uint32_t smem[];
    uint32_t* AhB = smem;                     // [2][ASZ]
    uint32_t* AlB = AhB + 2 * ASZ;
    uint32_t* BcB = AlB + 2 * ASZ;            // [2][BSZc]
    float* norms = reinterpret_cast<float*>(BcB + 2 * BSZc);  // [64]

    const uint32_t* Wc = g_Wc + layer * 32768;

    int t = threadIdx.x;
    int n0 = blockIdx.x * 64;
    int warp = t >> 5, lane = t & 31;
    int col_base = warp * 32;
    int gid = lane >> 2, tig = lane & 3;

    if (t < 64) norms[t] = 0.f;

    float acc[4][4][4];
#pragma unroll
    for (int mt = 0; mt < 4; ++mt)
#pragma unroll
        for (int nt = 0; nt < 4; ++nt)
#pragma unroll
            for (int c = 0; c < 4; ++c) acc[mt][nt][c] = 0.f;

    const float4* hin4 = reinterpret_cast<const float4*>(hin);
    const float4* s4   = reinterpret_cast<const float4*>(g_s);

    int m_[2], f_[2];
#pragma unroll
    for (int i = 0; i < 2; ++i) { int q = t + i * 128; m_[i] = q >> 2; f_[i] = q & 3; }

    auto load_a = [&](int ch, float4 v[2]) {   // ch = chunk 0..15 (16 k each)
        int kg = ch * 16;
#pragma unroll
        for (int i = 0; i < 2; ++i) {
            int grow = n0 + m_[i];
            v[i] = (kg < 128)
                 ? __ldg(hin4 + (size_t)grow * 32 + (kg >> 2) + f_[i])
                 : __ldg(s4   + (size_t)grow * 32 + ((kg - 128) >> 2) + f_[i]);
        }
    };
    auto store_a = [&](int buf, const float4 v[2]) {
        uint32_t* Ah = AhB + buf * ASZ;
        uint32_t* Al = AlB + buf * ASZ;
#pragma unroll
        for (int i = 0; i < 2; ++i) {
            uint32_t l01, l23;
            uint32_t h01 = bf16x2_split_hi(v[i].x, v[i].y, l01);
            uint32_t h23 = bf16x2_split_hi(v[i].z, v[i].w, l23);
            int base = m_[i] * 12 + f_[i] * 2;
            Ah[base] = h01; Ah[base + 1] = h23;
            Al[base] = l01; Al[base + 1] = l23;
        }
    };
    auto issue_b = [&](int ch, int buf) {
        uint32_t* B = BcB + buf * BSZc;
        const uint32_t* gW = Wc + ch * 2048;
#pragma unroll
        for (int i = 0; i < 4; ++i) {
            int off = t * 4 + i * 512;        // words
            cp_async16(B + off, gW + off);
        }
        asm volatile("cp.async.commit_group;");
    };

    float4 av[2];
    issue_b(0, 0);
    load_a(0, av);
    store_a(0, av);
    asm volatile("cp.async.wait_group 0;");
    __syncthreads();

    for (int kc = 0; kc < 16; ++kc) {
        int cur = kc & 1;
        float4 nav[2];
        if (kc < 15) {
            issue_b(kc + 1, cur ^ 1);
            load_a(kc + 1, nav);
        }

        {
            const uint32_t* Ah = AhB + cur * ASZ;
            const uint32_t* Al = AlB + cur * ASZ;
            const uint32_t* Bc = BcB + cur * BSZc;

            uint32_t bh[4][2], bl[4][2];
#pragma unroll
            for (int nt = 0; nt < 4; ++nt) {
                int j = col_base + nt * 8 + gid;
                uint4 bv = *reinterpret_cast<const uint4*>(Bc + j * 16 + tig * 4);
                bh[nt][0] = bv.x; bh[nt][1] = bv.y;
                bl[nt][0] = bv.z; bl[nt][1] = bv.w;
            }
#pragma unroll
            for (int mt = 0; mt < 4; ++mt) {
                int m = mt * 16 + gid;
                uint32_t ah[4], al[4];
                ah[0] = Ah[m * 12 + tig];
                ah[1] = Ah[(m + 8) * 12 + tig];
                ah[2] = Ah[m * 12 + tig + 4];
                ah[3] = Ah[(m + 8) * 12 + tig + 4];
                al[0] = Al[m * 12 + tig];
                al[1] = Al[(m + 8) * 12 + tig];
                al[2] = Al[m * 12 + tig + 4];
                al[3] = Al[(m + 8) * 12 + tig + 4];
#pragma unroll
                for (int nt = 0; nt < 4; ++nt) {
                    MMA_BF16(acc[mt][nt], ah, bh[nt]);
                    MMA_BF16(acc[mt][nt], ah, bl[nt]);
                    MMA_BF16(acc[mt][nt], al, bh[nt]);
                }
            }
        }

        if (kc < 15) store_a(cur ^ 1, nav);
        asm volatile("cp.async.wait_group 0;");
        __syncthreads();
    }

    // ---- epilogue: bias + relu + row L2 norm (+ optional fp16 copy) ----
    float2 bias[4];
#pragma unroll
    for (int nt = 0; nt < 4; ++nt)
        bias[nt] = __ldg(reinterpret_cast<const float2*>(b) +
                         (col_base + nt * 8 + 2 * tig) / 2);

#pragma unroll
    for (int mt = 0; mt < 4; ++mt) {
#pragma unroll
        for (int r = 0; r < 2; ++r) {
            float part = 0.f;
#pragma unroll
            for (int nt = 0; nt < 4; ++nt) {
                float y0 = fmaxf(acc[mt][nt][2 * r]     + bias[nt].x, 0.f);
                float y1 = fmaxf(acc[mt][nt][2 * r + 1] + bias[nt].y, 0.f);
                acc[mt][nt][2 * r]     = y0;
                acc[mt][nt][2 * r + 1] = y1;
                part += y0 * y0 + y1 * y1;
            }
            part += __shfl_xor_sync(0xffffffffu, part, 1);
            part += __shfl_xor_sync(0xffffffffu, part, 2);
            if (tig == 0)
                atomicAdd(&norms[mt * 16 + gid + r * 8], part);
        }
    }
    __syncthreads();

#pragma unroll
    for (int mt = 0; mt < 4; ++mt) {
#pragma unroll
        for (int r = 0; r < 2; ++r) {
            int lrow = mt * 16 + gid + r * 8;
            int grow = n0 + lrow;
            float sc = 1.0f / fmaxf(sqrtf(norms[lrow]), 1e-12f);
#pragma unroll
            for (int nt = 0; nt < 4; ++nt) {
                int col = col_base + nt * 8 + 2 * tig;
                float2 o = make_float2(acc[mt][nt][2 * r] * sc,
                                       acc[mt][nt][2 * r + 1] * sc);
                *reinterpret_cast<float2*>(out + (size_t)grow * F + col) = o;
                if (write16)
                    g_f16[(size_t)grow * 64 + (col >> 1)] = pack_h2(o.x, o.y);
            }
        }
    }
}

// ---------------- layer 2a: project fp16 h2 -> pself(+bias) [N,16] and fp16 pn ----------------
// warp per node; lane l covers features {2l, 2l+1, 64+2l, 64+2l+1} from g_f16.
// W read as coalesced float2 (lane-stride 8B). pn packed fp16 into g_s.
__global__ __launch_bounds__(256) void proj32_kernel(
    const float* __restrict__ W,     // [16,256]
    const float* __restrict__ b)     // [16]
{
    int n = (blockIdx.x * blockDim.x + threadIdx.x) >> 5;
    if (n >= N_NODES) return;
    int l = threadIdx.x & 31;

    float2 x0 = unpack_h2(__ldg(g_f16 + (size_t)n * 64 + l));
    float2 x1 = unpack_h2(__ldg(g_f16 + (size_t)n * 64 + 32 + l));
    const float2* Wf2 = reinterpret_cast<const float2*>(W);

    float ps[16], pn[16];
#pragma unroll
    for (int j = 0; j < 16; ++j) {
        float2 ws0 = __ldg(Wf2 + j * 128 + l);
        float2 ws1 = __ldg(Wf2 + j * 128 + 32 + l);
        float2 wn0 = __ldg(Wf2 + j * 128 + 64 + l);
        float2 wn1 = __ldg(Wf2 + j * 128 + 96 + l);
        float as = x0.x * ws0.x + x0.y * ws0.y + x1.x * ws1.x + x1.y * ws1.y;
        float an = x0.x * wn0.x + x0.y * wn0.y + x1.x * wn1.x + x1.y * wn1.y;
#pragma unroll
        for (int off = 16; off; off >>= 1) {
            as += __shfl_xor_sync(0xffffffffu, as, off);
            an += __shfl_xor_sync(0xffffffffu, an, off);
        }
        ps[j] = as; pn[j] = an;
    }
    if (l < 16)
        g_h1[(size_t)n * 16 + l] = ps[l] + __ldg(b + l);
    if (l < 8)
        reinterpret_cast<uint32_t*>(g_s)[(size_t)n * 8 + l] =
            pack_h2(pn[2 * l], pn[2 * l + 1]);
}

// ---------------- layer 2b: fp16 16-dim aggregation + final add (+ state reset) ----------------
__global__ __launch_bounds__(256) void agg16_kernel(float* __restrict__ out) {
    int n = (blockIdx.x * blockDim.x + threadIdx.x) >> 5;
    if (n >= N_NODES) return;
    int lane = threadIdx.x & 31;
    int f = lane & 15, half = lane >> 4;
    int beg = g_off[n];
    int end = beg + g_cnt[n];
    const __half* pn16 = reinterpret_cast<const __half*>(g_s);

    float acc = 0.f;
    for (int e = beg + half; e < end; e += 2) {
        int2 ew = __ldg(g_edge + e);
        float v = __half2float(__ldg(pn16 + (size_t)ew.x * 16 + f));
        acc += __int_as_float(ew.y) * v;
    }
    acc += __shfl_xor_sync(0xffffffffu, acc, 16);

    if (lane < 16) {
        float inv = (end > beg) ? 1.0f / (float)(end - beg) : 0.0f;
        out[(size_t)n * NCLS + f] = g_h1[(size_t)n * 16 + f] + acc * inv;
    }
    // reset counters for the NEXT invocation (statics start zeroed)
    if (lane == 31) g_cnt[n] = 0;
    if (n == 0 && lane == 30) g_cursor = 0;
}

// ---------------- launch ----------------
extern "C" void kernel_launch(void* const* d_in, const int* in_sizes, int n_in,
                              void* d_out, int out_size) {
    const float* h  = (const float*)d_in[0];
    const float* w  = (const float*)d_in[1];
    const int* src  = (const int*)d_in[2];
    const int* dst  = (const int*)d_in[3];
    const float* W0 = (const float*)d_in[4];
    const float* b0 = (const float*)d_in[5];
    const float* W1 = (const float*)d_in[6];
    const float* b1 = (const float*)d_in[7];
    const float* W2 = (const float*)d_in[8];
    const float* b2 = (const float*)d_in[9];
    float* out = (float*)d_out;

    void *ph1 = nullptr, *ph2 = nullptr;
    cudaGetSymbolAddress(&ph1, g_h1);
    cudaGetSymbolAddress(&ph2, g_h2);
    float* h1 = (float*)ph1;
    float* h2 = (float*)ph2;

    cudaFuncSetAttribute(sage_gemm_bf16,
                         cudaFuncAttributeMaxDynamicSharedMemorySize,
                         GEMM_SMEM_BYTES);

    const int NODE_BLOCKS  = (N_NODES + 255) / 256;            // 157
    const int WARPN_BLOCKS = (N_NODES * 32 + 255) / 256;       // 5000
    const int GEMM_BLOCKS  = (N_NODES + 63) / 64;              // 625

    // CSR build + fp16 conversion + weight pre-split (one fused launch + 2)
    hist_conv_wsplit_kernel<<<EDGE_BLOCKS + CONV_BLOCKS + WSP_BLOCKS, 256>>>(
        dst, (const float4*)h, W0, W1);
    offsets_kernel<<<NODE_BLOCKS, 256>>>();
    scatter_kernel<<<EDGE_BLOCKS, 256>>>(src, dst, w);

    // layer 0 (gemm emits fp16 h1 into g_f16 for layer-1 agg)
    agg_csr_kernel<<<WARPN_BLOCKS, 256>>>();
    sage_gemm_bf16<<<GEMM_BLOCKS, 128, GEMM_SMEM_BYTES>>>(h, b0, h1, 0, 1);

    // layer 1 (gemm also emits fp16 h2 for layer-2 proj)
    agg_csr_kernel<<<WARPN_BLOCKS, 256>>>();
    sage_gemm_bf16<<<GEMM_BLOCKS, 128, GEMM_SMEM_BYTES>>>(h1, b1, h2, 1, 1);

    // layer 2: project first (linearity), then 16-dim fp16 aggregate
    proj32_kernel<<<WARPN_BLOCKS, 256>>>(W2, b2);
    agg16_kernel<<<WARPN_BLOCKS, 256>>>(out);
}